// round 1
// baseline (speedup 1.0000x reference)
#include <cuda_runtime.h>

#define KNB 16
#define NL 3

typedef unsigned long long u64;

__device__ __forceinline__ u64 pack2(float lo, float hi){
    u64 r; asm("mov.b64 %0, {%1,%2};" : "=l"(r) : "f"(lo), "f"(hi)); return r;
}
__device__ __forceinline__ void unpack2(u64 v, float& lo, float& hi){
    asm("mov.b64 {%0,%1}, %2;" : "=f"(lo), "=f"(hi) : "l"(v));
}
__device__ __forceinline__ u64 ffma2(u64 a, u64 b, u64 c){
    u64 d; asm("fma.rn.f32x2 %0, %1, %2, %3;" : "=l"(d) : "l"(a), "l"(b), "l"(c)); return d;
}
__device__ __forceinline__ u64 fmul2(u64 a, u64 b){
    u64 d; asm("mul.rn.f32x2 %0, %1, %2;" : "=l"(d) : "l"(a), "l"(b)); return d;
}
__device__ __forceinline__ u64 fadd2(u64 a, u64 b){
    u64 d; asm("add.rn.f32x2 %0, %1, %2;" : "=l"(d) : "l"(a), "l"(b)); return d;
}

// lrelu(x) = max(x, 0.2x) = 0.6x + 0.4|x|   (branchless, packed)
__device__ __forceinline__ u64 lrelu2(u64 x, u64 c06, u64 c04){
    u64 ax = x & 0x7fffffff7fffffffULL;
    return ffma2(ax, c04, fmul2(x, c06));
}

__global__ __launch_bounds__(256, 2)
void atom_mp_kernel(const float* __restrict__ dist,
                    const float* __restrict__ at,
                    const float* __restrict__ W1, const float* __restrict__ b1,
                    const float* __restrict__ W2, const float* __restrict__ b2,
                    const float* __restrict__ gw, const float* __restrict__ gb,
                    float* __restrict__ out, int P)
{
    // Duplicated-weight smem tables: one LDS.128 = two pre-splatted f32x2 weights.
    __shared__ ulonglong2 sW1[NL*13*7];   // [l][r][cc] cols (2cc, 2cc+1), col 13 = 0 pad
    __shared__ ulonglong2 sW2[NL*13*3];   // [l][r][cc] cols (2cc, 2cc+1)
    __shared__ u64  sB1[NL*13];
    __shared__ u64  sB2[NL*6];
    __shared__ float sGW[NL*6], sGB[NL*6];

    const int tid = threadIdx.x;
    for (int i = tid; i < NL*13*7; i += 256) {
        int l = i / 91, rr = i % 91, r = rr / 7, cc = rr % 7;
        int c0 = 2*cc;
        float w0 = W1[l*169 + r*13 + c0];
        float w1 = (c0 + 1 < 13) ? W1[l*169 + r*13 + c0 + 1] : 0.0f;
        sW1[i] = make_ulonglong2(pack2(w0, w0), pack2(w1, w1));
    }
    for (int i = tid; i < NL*13*3; i += 256) {
        int l = i / 39, rr = i % 39, r = rr / 3, cc = rr % 3;
        float w0 = W2[l*78 + r*6 + 2*cc];
        float w1 = W2[l*78 + r*6 + 2*cc + 1];
        sW2[i] = make_ulonglong2(pack2(w0, w0), pack2(w1, w1));
    }
    if (tid < NL*13) sB1[tid] = pack2(b1[tid], b1[tid]);
    if (tid < NL*6)  { sB2[tid] = pack2(b2[tid], b2[tid]); sGW[tid] = gw[tid]; sGB[tid] = gb[tid]; }
    __syncthreads();

    int gt  = blockIdx.x * 256 + tid;
    int p0  = gt >> 2;                 // point index
    int sub = gt & 3;                  // which 4-neighbor slice of the point
    bool valid = (p0 < P);
    int p = valid ? p0 : (P - 1);      // clamp: keep warps converged for shfl

    // ---- load 4 neighbors (atomtypes: 24 contiguous floats = 6 float4) ----
    const float4* atq = (const float4*)(at + (size_t)p * (KNB*6) + sub * 24);
    float4 a0 = atq[0], a1 = atq[1], a2 = atq[2], a3 = atq[3], a4 = atq[4], a5 = atq[5];
    u64 atP0[6], atP1[6];              // packed pairs {n0,n1}, {n2,n3}
    atP0[0] = pack2(a0.x, a1.z); atP0[1] = pack2(a0.y, a1.w);
    atP0[2] = pack2(a0.z, a2.x); atP0[3] = pack2(a0.w, a2.y);
    atP0[4] = pack2(a1.x, a2.z); atP0[5] = pack2(a1.y, a2.w);
    atP1[0] = pack2(a3.x, a4.z); atP1[1] = pack2(a3.y, a4.w);
    atP1[2] = pack2(a3.z, a5.x); atP1[3] = pack2(a3.w, a5.y);
    atP1[4] = pack2(a4.x, a5.z); atP1[5] = pack2(a4.y, a5.w);

    float4 dq = *(const float4*)(dist + (size_t)p * KNB + sub * 4);
    u64 dP0 = pack2(dq.x, dq.y), dP1 = pack2(dq.z, dq.w);

    const u64 c06 = pack2(0.6f, 0.6f), c04 = pack2(0.4f, 0.4f);

    float pe[6];
    #pragma unroll
    for (int c = 0; c < 6; c++) pe[c] = 1.0f;

    #pragma unroll 1
    for (int l = 0; l < NL; l++) {
        u64 pe2[6];
        #pragma unroll
        for (int c = 0; c < 6; c++) pe2[c] = pack2(pe[c], pe[c]);

        // ---- h = lrelu(feat @ W1 + b1), feat = [pe | at | dist] (13) ----
        u64 h0[13], h1[13];
        #pragma unroll
        for (int c = 0; c < 13; c++) { u64 b = sB1[l*13 + c]; h0[c] = b; h1[c] = b; }

        const ulonglong2* w1p = &sW1[l*91];
        #pragma unroll
        for (int r = 0; r < 13; r++) {
            u64 f0, f1;
            if (r < 6)       { f0 = pe2[r];     f1 = pe2[r];     }
            else if (r < 12) { f0 = atP0[r-6];  f1 = atP1[r-6];  }
            else             { f0 = dP0;        f1 = dP1;        }
            #pragma unroll
            for (int cc = 0; cc < 7; cc++) {
                ulonglong2 w = w1p[r*7 + cc];
                h0[2*cc] = ffma2(f0, w.x, h0[2*cc]);
                h1[2*cc] = ffma2(f1, w.x, h1[2*cc]);
                if (cc < 6) {
                    h0[2*cc+1] = ffma2(f0, w.y, h0[2*cc+1]);
                    h1[2*cc+1] = ffma2(f1, w.y, h1[2*cc+1]);
                }
            }
        }
        #pragma unroll
        for (int c = 0; c < 13; c++) { h0[c] = lrelu2(h0[c], c06, c04); h1[c] = lrelu2(h1[c], c06, c04); }

        // ---- contrib = h @ W2 + b2 (per neighbor; sum includes K copies of b2) ----
        u64 m0[6], m1[6];
        #pragma unroll
        for (int c = 0; c < 6; c++) { u64 b = sB2[l*6 + c]; m0[c] = b; m1[c] = b; }
        const ulonglong2* w2p = &sW2[l*39];
        #pragma unroll
        for (int r = 0; r < 13; r++) {
            #pragma unroll
            for (int cc = 0; cc < 3; cc++) {
                ulonglong2 w = w2p[r*3 + cc];
                m0[2*cc]   = ffma2(h0[r], w.x, m0[2*cc]);
                m1[2*cc]   = ffma2(h1[r], w.x, m1[2*cc]);
                m0[2*cc+1] = ffma2(h0[r], w.y, m0[2*cc+1]);
                m1[2*cc+1] = ffma2(h1[r], w.y, m1[2*cc+1]);
            }
        }

        // ---- reduce over 16 neighbors: in-thread (4) then quad butterfly ----
        float msg[6];
        #pragma unroll
        for (int c = 0; c < 6; c++) {
            float lo, hi;
            unpack2(fadd2(m0[c], m1[c]), lo, hi);
            msg[c] = lo + hi;
        }
        #pragma unroll
        for (int c = 0; c < 6; c++) {
            msg[c] += __shfl_xor_sync(0xffffffffu, msg[c], 1);
            msg[c] += __shfl_xor_sync(0xffffffffu, msg[c], 2);
        }

        // ---- GroupNorm(2 groups of 3) + lrelu + residual (redundant per lane) ----
        float mu0 = (msg[0] + msg[1] + msg[2]) * (1.0f/3.0f);
        float mu1 = (msg[3] + msg[4] + msg[5]) * (1.0f/3.0f);
        float ev[6];
        ev[0] = msg[0] - mu0; ev[1] = msg[1] - mu0; ev[2] = msg[2] - mu0;
        ev[3] = msg[3] - mu1; ev[4] = msg[4] - mu1; ev[5] = msg[5] - mu1;
        float rs0 = rsqrtf((ev[0]*ev[0] + ev[1]*ev[1] + ev[2]*ev[2]) * (1.0f/3.0f) + 1e-5f);
        float rs1 = rsqrtf((ev[3]*ev[3] + ev[4]*ev[4] + ev[5]*ev[5]) * (1.0f/3.0f) + 1e-5f);
        #pragma unroll
        for (int c = 0; c < 6; c++) {
            float xn = ev[c] * (c < 3 ? rs0 : rs1);
            float y  = xn * sGW[l*6 + c] + sGB[l*6 + c];
            pe[c] += fmaxf(y, 0.2f * y);
        }
    }

    if (valid) {
        float* o = out + (size_t)p * 6;
        #pragma unroll
        for (int c = sub; c < 6; c += 4) o[c] = pe[c];
    }
}

extern "C" void kernel_launch(void* const* d_in, const int* in_sizes, int n_in,
                              void* d_out, int out_size)
{
    const float* dist = (const float*)d_in[0];
    const float* at   = (const float*)d_in[1];
    const float* W1   = (const float*)d_in[2];
    const float* b1   = (const float*)d_in[3];
    const float* W2   = (const float*)d_in[4];
    const float* b2   = (const float*)d_in[5];
    const float* gw   = (const float*)d_in[6];
    const float* gb   = (const float*)d_in[7];

    int P = in_sizes[0] / KNB;                    // B*N points (dist = P*K elements)
    int threads = 256;
    int blocks  = (P * 4 + threads - 1) / threads;
    atom_mp_kernel<<<blocks, threads>>>(dist, at, W1, b1, W2, b2, gw, gb,
                                        (float*)d_out, P);
}

// round 4
// speedup vs baseline: 1.0878x; 1.0878x over previous
#include <cuda_runtime.h>

#define KNB 16
#define NL 3

typedef unsigned long long u64;

__device__ __forceinline__ u64 pack2(float lo, float hi){
    u64 r; asm("mov.b64 %0, {%1,%2};" : "=l"(r) : "f"(lo), "f"(hi)); return r;
}
__device__ __forceinline__ void unpack2(u64 v, float& lo, float& hi){
    asm("mov.b64 {%0,%1}, %2;" : "=f"(lo), "=f"(hi) : "l"(v));
}
__device__ __forceinline__ u64 ffma2(u64 a, u64 b, u64 c){
    u64 d; asm("fma.rn.f32x2 %0, %1, %2, %3;" : "=l"(d) : "l"(a), "l"(b), "l"(c)); return d;
}
__device__ __forceinline__ u64 fmul2(u64 a, u64 b){
    u64 d; asm("mul.rn.f32x2 %0, %1, %2;" : "=l"(d) : "l"(a), "l"(b)); return d;
}
__device__ __forceinline__ u64 fadd2(u64 a, u64 b){
    u64 d; asm("add.rn.f32x2 %0, %1, %2;" : "=l"(d) : "l"(a), "l"(b)); return d;
}

// lrelu(x) = max(x, 0.2x) = 0.6x + 0.4|x|   (branchless, packed)
__device__ __forceinline__ u64 lrelu2(u64 x, u64 c06, u64 c04){
    u64 ax = x & 0x7fffffff7fffffffULL;
    return ffma2(ax, c04, fmul2(x, c06));
}

__global__ __launch_bounds__(256, 2)
void atom_mp_kernel(const float* __restrict__ dist,
                    const float* __restrict__ at,
                    const float* __restrict__ W1, const float* __restrict__ b1,
                    const float* __restrict__ W2, const float* __restrict__ b2,
                    const float* __restrict__ gw, const float* __restrict__ gb,
                    float* __restrict__ out, int P)
{
    // sW1c: natural column-pair table for rows 0..5 (pe rows), used for the shared base.
    //   [l][r][cc] = {W1[r][2cc], W1[r][2cc+1] or 0}, cc=0..6, row stride 8 for alignment.
    __shared__ u64 sW1c[NL*6*8];
    __shared__ u64 sB1c[NL*8];            // {b1[2cc], b1[2cc+1] or 0}
    // sW1d: duplicated (pre-splatted) pairs for rows 6..12 (per-neighbor rows).
    //   [l][r-6][cc]: .x = {w(2cc),w(2cc)}, .y = {w(2cc+1),w(2cc+1)}
    __shared__ ulonglong2 sW1d[NL*7*7];
    __shared__ ulonglong2 sW2d[NL*13*3];  // duplicated W2 col pairs
    __shared__ u64  sB2[NL*6];
    __shared__ float sGW[NL*6], sGB[NL*6];

    const int tid = threadIdx.x;
    // rows 0..5 natural col pairs
    for (int i = tid; i < NL*6*7; i += 256) {
        int l = i / 42, rr = i % 42, r = rr / 7, cc = rr % 7;
        int c0 = 2*cc;
        float w0 = W1[l*169 + r*13 + c0];
        float w1 = (c0 + 1 < 13) ? W1[l*169 + r*13 + c0 + 1] : 0.0f;
        sW1c[(l*6 + r)*8 + cc] = pack2(w0, w1);
    }
    if (tid < NL*8) {
        int l = tid / 8, cc = tid % 8;
        float v0 = (2*cc < 13)     ? b1[l*13 + 2*cc]     : 0.0f;
        float v1 = (2*cc + 1 < 13) ? b1[l*13 + 2*cc + 1] : 0.0f;
        sB1c[tid] = pack2(v0, v1);
    }
    // rows 6..12 duplicated pairs
    for (int i = tid; i < NL*7*7; i += 256) {
        int l = i / 49, rr = i % 49, r = rr / 7 + 6, cc = rr % 7;
        int c0 = 2*cc;
        float w0 = W1[l*169 + r*13 + c0];
        float w1 = (c0 + 1 < 13) ? W1[l*169 + r*13 + c0 + 1] : 0.0f;
        sW1d[i] = make_ulonglong2(pack2(w0, w0), pack2(w1, w1));
    }
    for (int i = tid; i < NL*13*3; i += 256) {
        int l = i / 39, rr = i % 39, r = rr / 3, cc = rr % 3;
        float w0 = W2[l*78 + r*6 + 2*cc];
        float w1 = W2[l*78 + r*6 + 2*cc + 1];
        sW2d[i] = make_ulonglong2(pack2(w0, w0), pack2(w1, w1));
    }
    if (tid < NL*6)  { sB2[tid] = pack2(b2[tid], b2[tid]); sGW[tid] = gw[tid]; sGB[tid] = gb[tid]; }
    __syncthreads();

    int gt  = blockIdx.x * 256 + tid;
    int p0  = gt >> 2;                 // point index
    int sub = gt & 3;                  // which 4-neighbor slice of the point
    bool valid = (p0 < P);
    int p = valid ? p0 : (P - 1);      // clamp: keep warps converged for shfl

    // ---- load 4 neighbors (atomtypes: 24 contiguous floats = 6 float4) ----
    const float4* atq = (const float4*)(at + (size_t)p * (KNB*6) + sub * 24);
    float4 a0 = atq[0], a1 = atq[1], a2 = atq[2], a3 = atq[3], a4 = atq[4], a5 = atq[5];
    u64 atP0[6], atP1[6];              // packed pairs {n0,n1}, {n2,n3}
    atP0[0] = pack2(a0.x, a1.z); atP0[1] = pack2(a0.y, a1.w);
    atP0[2] = pack2(a0.z, a2.x); atP0[3] = pack2(a0.w, a2.y);
    atP0[4] = pack2(a1.x, a2.z); atP0[5] = pack2(a1.y, a2.w);
    atP1[0] = pack2(a3.x, a4.z); atP1[1] = pack2(a3.y, a4.w);
    atP1[2] = pack2(a3.z, a5.x); atP1[3] = pack2(a3.w, a5.y);
    atP1[4] = pack2(a4.x, a5.z); atP1[5] = pack2(a4.y, a5.w);

    float4 dq = *(const float4*)(dist + (size_t)p * KNB + sub * 4);
    u64 dP0 = pack2(dq.x, dq.y), dP1 = pack2(dq.z, dq.w);

    const u64 c06 = pack2(0.6f, 0.6f), c04 = pack2(0.4f, 0.4f);

    float pe[6];
    #pragma unroll
    for (int c = 0; c < 6; c++) pe[c] = 1.0f;

    #pragma unroll 1
    for (int l = 0; l < NL; l++) {
        // ---- shared base: b1 + pe @ W1[rows 0..5], column-packed (neighbor-invariant) ----
        u64 bc[7];
        #pragma unroll
        for (int cc = 0; cc < 7; cc++) bc[cc] = sB1c[l*8 + cc];
        #pragma unroll
        for (int r = 0; r < 6; r++) {
            u64 f = pack2(pe[r], pe[r]);
            #pragma unroll
            for (int cc = 0; cc < 7; cc++)
                bc[cc] = ffma2(f, sW1c[(l*6 + r)*8 + cc], bc[cc]);
        }

        // ---- unpack base to scalars, splat into neighbor-packed accumulators ----
        u64 h0[13], h1[13];
        #pragma unroll
        for (int cc = 0; cc < 7; cc++) {
            float lo, hi;
            unpack2(bc[cc], lo, hi);
            u64 s0 = pack2(lo, lo);
            h0[2*cc] = s0; h1[2*cc] = s0;
            if (cc < 6) {
                u64 s1 = pack2(hi, hi);
                h0[2*cc+1] = s1; h1[2*cc+1] = s1;
            }
        }

        // ---- per-neighbor rows 6..12 (atomtypes + dist), neighbor-packed ----
        const ulonglong2* w1p = &sW1d[l*49];
        #pragma unroll
        for (int r = 0; r < 7; r++) {
            u64 f0, f1;
            if (r < 6) { f0 = atP0[r]; f1 = atP1[r]; }
            else       { f0 = dP0;     f1 = dP1;     }
            #pragma unroll
            for (int cc = 0; cc < 7; cc++) {
                ulonglong2 w = w1p[r*7 + cc];
                h0[2*cc] = ffma2(f0, w.x, h0[2*cc]);
                h1[2*cc] = ffma2(f1, w.x, h1[2*cc]);
                if (cc < 6) {
                    h0[2*cc+1] = ffma2(f0, w.y, h0[2*cc+1]);
                    h1[2*cc+1] = ffma2(f1, w.y, h1[2*cc+1]);
                }
            }
        }
        #pragma unroll
        for (int c = 0; c < 13; c++) { h0[c] = lrelu2(h0[c], c06, c04); h1[c] = lrelu2(h1[c], c06, c04); }

        // ---- contrib = h @ W2 + b2 (per neighbor; sum includes K copies of b2) ----
        u64 m0[6], m1[6];
        #pragma unroll
        for (int c = 0; c < 6; c++) { u64 b = sB2[l*6 + c]; m0[c] = b; m1[c] = b; }
        const ulonglong2* w2p = &sW2d[l*39];
        #pragma unroll
        for (int r = 0; r < 13; r++) {
            #pragma unroll
            for (int cc = 0; cc < 3; cc++) {
                ulonglong2 w = w2p[r*3 + cc];
                m0[2*cc]   = ffma2(h0[r], w.x, m0[2*cc]);
                m1[2*cc]   = ffma2(h1[r], w.x, m1[2*cc]);
                m0[2*cc+1] = ffma2(h0[r], w.y, m0[2*cc+1]);
                m1[2*cc+1] = ffma2(h1[r], w.y, m1[2*cc+1]);
            }
        }

        // ---- reduce over 16 neighbors: in-thread (4) then quad butterfly ----
        float msg[6];
        #pragma unroll
        for (int c = 0; c < 6; c++) {
            float lo, hi;
            unpack2(fadd2(m0[c], m1[c]), lo, hi);
            msg[c] = lo + hi;
        }
        #pragma unroll
        for (int c = 0; c < 6; c++) {
            msg[c] += __shfl_xor_sync(0xffffffffu, msg[c], 1);
            msg[c] += __shfl_xor_sync(0xffffffffu, msg[c], 2);
        }

        // ---- GroupNorm(2 groups of 3) + lrelu + residual (redundant per lane) ----
        float mu0 = (msg[0] + msg[1] + msg[2]) * (1.0f/3.0f);
        float mu1 = (msg[3] + msg[4] + msg[5]) * (1.0f/3.0f);
        float ev[6];
        ev[0] = msg[0] - mu0; ev[1] = msg[1] - mu0; ev[2] = msg[2] - mu0;
        ev[3] = msg[3] - mu1; ev[4] = msg[4] - mu1; ev[5] = msg[5] - mu1;
        float rs0 = rsqrtf((ev[0]*ev[0] + ev[1]*ev[1] + ev[2]*ev[2]) * (1.0f/3.0f) + 1e-5f);
        float rs1 = rsqrtf((ev[3]*ev[3] + ev[4]*ev[4] + ev[5]*ev[5]) * (1.0f/3.0f) + 1e-5f);
        #pragma unroll
        for (int c = 0; c < 6; c++) {
            float xn = ev[c] * (c < 3 ? rs0 : rs1);
            float y  = xn * sGW[l*6 + c] + sGB[l*6 + c];
            pe[c] += fmaxf(y, 0.2f * y);
        }
    }

    if (valid) {
        float* o = out + (size_t)p * 6;
        #pragma unroll
        for (int c = sub; c < 6; c += 4) o[c] = pe[c];
    }
}

extern "C" void kernel_launch(void* const* d_in, const int* in_sizes, int n_in,
                              void* d_out, int out_size)
{
    const float* dist = (const float*)d_in[0];
    const float* at   = (const float*)d_in[1];
    const float* W1   = (const float*)d_in[2];
    const float* b1   = (const float*)d_in[3];
    const float* W2   = (const float*)d_in[4];
    const float* b2   = (const float*)d_in[5];
    const float* gw   = (const float*)d_in[6];
    const float* gb   = (const float*)d_in[7];

    int P = in_sizes[0] / KNB;                    // B*N points (dist = P*K elements)
    int threads = 256;
    int blocks  = (P * 4 + threads - 1) / threads;
    atom_mp_kernel<<<blocks, threads>>>(dist, at, W1, b1, W2, b2, gw, gb,
                                        (float*)d_out, P);
}

// round 5
// speedup vs baseline: 1.2465x; 1.1459x over previous
#include <cuda_runtime.h>

#define KNB 16
#define NL 3

typedef unsigned long long u64;

__device__ __forceinline__ u64 pack2(float lo, float hi){
    u64 r; asm("mov.b64 %0, {%1,%2};" : "=l"(r) : "f"(lo), "f"(hi)); return r;
}
__device__ __forceinline__ void unpack2(u64 v, float& lo, float& hi){
    asm("mov.b64 {%0,%1}, %2;" : "=f"(lo), "=f"(hi) : "l"(v));
}
__device__ __forceinline__ u64 ffma2(u64 a, u64 b, u64 c){
    u64 d; asm("fma.rn.f32x2 %0, %1, %2, %3;" : "=l"(d) : "l"(a), "l"(b), "l"(c)); return d;
}
__device__ __forceinline__ u64 fmul2(u64 a, u64 b){
    u64 d; asm("mul.rn.f32x2 %0, %1, %2;" : "=l"(d) : "l"(a), "l"(b)); return d;
}
__device__ __forceinline__ u64 fadd2(u64 a, u64 b){
    u64 d; asm("add.rn.f32x2 %0, %1, %2;" : "=l"(d) : "l"(a), "l"(b)); return d;
}

// lrelu(x) = max(x, 0.2x) = 0.6x + 0.4|x|   (branchless, packed)
__device__ __forceinline__ u64 lrelu2(u64 x, u64 c06, u64 c04){
    u64 ax = x & 0x7fffffff7fffffffULL;
    return ffma2(ax, c04, fmul2(x, c06));
}

#define TPB 128

__global__ __launch_bounds__(TPB, 2)
void atom_mp_kernel(const float* __restrict__ dist,
                    const float* __restrict__ at,
                    const float* __restrict__ W1, const float* __restrict__ b1,
                    const float* __restrict__ W2, const float* __restrict__ b2,
                    const float* __restrict__ gw, const float* __restrict__ gb,
                    float* __restrict__ out, int P)
{
    // sW1c: natural column-pair table for rows 0..5 (pe rows) -> shared base.
    __shared__ u64 sW1c[NL*6*8];
    __shared__ u64 sB1c[NL*8];
    // sW1d: duplicated (pre-splatted) pairs for rows 6..12.
    __shared__ ulonglong2 sW1d[NL*7*7];
    __shared__ ulonglong2 sW2d[NL*13*3];
    __shared__ u64  sB2[NL*6];           // holds 4*b2 pre-splatted (one m-acc covers 4 packs)
    __shared__ float sGW[NL*6], sGB[NL*6];

    const int tid = threadIdx.x;
    for (int i = tid; i < NL*6*7; i += TPB) {
        int l = i / 42, rr = i % 42, r = rr / 7, cc = rr % 7;
        int c0 = 2*cc;
        float w0 = W1[l*169 + r*13 + c0];
        float w1 = (c0 + 1 < 13) ? W1[l*169 + r*13 + c0 + 1] : 0.0f;
        sW1c[(l*6 + r)*8 + cc] = pack2(w0, w1);
    }
    if (tid < NL*8) {
        int l = tid / 8, cc = tid % 8;
        float v0 = (2*cc < 13)     ? b1[l*13 + 2*cc]     : 0.0f;
        float v1 = (2*cc + 1 < 13) ? b1[l*13 + 2*cc + 1] : 0.0f;
        sB1c[tid] = pack2(v0, v1);
    }
    for (int i = tid; i < NL*7*7; i += TPB) {
        int l = i / 49, rr = i % 49, r = rr / 7 + 6, cc = rr % 7;
        int c0 = 2*cc;
        float w0 = W1[l*169 + r*13 + c0];
        float w1 = (c0 + 1 < 13) ? W1[l*169 + r*13 + c0 + 1] : 0.0f;
        sW1d[i] = make_ulonglong2(pack2(w0, w0), pack2(w1, w1));
    }
    for (int i = tid; i < NL*13*3; i += TPB) {
        int l = i / 39, rr = i % 39, r = rr / 3, cc = rr % 3;
        float w0 = W2[l*78 + r*6 + 2*cc];
        float w1 = W2[l*78 + r*6 + 2*cc + 1];
        sW2d[i] = make_ulonglong2(pack2(w0, w0), pack2(w1, w1));
    }
    if (tid < NL*6)  {
        float b4 = 4.0f * b2[tid];
        sB2[tid] = pack2(b4, b4);
        sGW[tid] = gw[tid]; sGB[tid] = gb[tid];
    }
    __syncthreads();

    int gt  = blockIdx.x * TPB + tid;
    int p0  = gt >> 1;                 // point index (2 threads per point)
    int sub = gt & 1;                  // which 8-neighbor half
    bool valid = (p0 < P);
    int p = valid ? p0 : (P - 1);      // clamp: keep warps converged for shfl

    // ---- load 8 neighbors: 48 contiguous floats of atomtypes + 8 dists ----
    float arr[48];
    {
        const float4* atq = (const float4*)(at + (size_t)p * (KNB*6) + sub * 48);
        float4* arv = (float4*)arr;
        #pragma unroll
        for (int i = 0; i < 12; i++) arv[i] = atq[i];
    }
    u64 atQ[4][6];                     // pack q = neighbors (2q, 2q+1)
    #pragma unroll
    for (int q = 0; q < 4; q++)
        #pragma unroll
        for (int d = 0; d < 6; d++)
            atQ[q][d] = pack2(arr[12*q + d], arr[12*q + 6 + d]);

    u64 dQ[4];
    {
        float darr[8];
        float4* drv = (float4*)darr;
        const float4* dq4 = (const float4*)(dist + (size_t)p * KNB + sub * 8);
        drv[0] = dq4[0]; drv[1] = dq4[1];
        #pragma unroll
        for (int q = 0; q < 4; q++) dQ[q] = pack2(darr[2*q], darr[2*q+1]);
    }

    const u64 c06 = pack2(0.6f, 0.6f), c04 = pack2(0.4f, 0.4f);

    float pe[6];
    #pragma unroll
    for (int c = 0; c < 6; c++) pe[c] = 1.0f;

    #pragma unroll 1
    for (int l = 0; l < NL; l++) {
        // ---- shared base: b1 + pe @ W1[rows 0..5], column-packed (neighbor-invariant) ----
        u64 bc[7];
        #pragma unroll
        for (int cc = 0; cc < 7; cc++) bc[cc] = sB1c[l*8 + cc];
        #pragma unroll
        for (int r = 0; r < 6; r++) {
            u64 f = pack2(pe[r], pe[r]);
            #pragma unroll
            for (int cc = 0; cc < 7; cc++)
                bc[cc] = ffma2(f, sW1c[(l*6 + r)*8 + cc], bc[cc]);
        }
        // unpack base to splatted scalars sb[13]
        u64 sb[13];
        #pragma unroll
        for (int cc = 0; cc < 7; cc++) {
            float lo, hi;
            unpack2(bc[cc], lo, hi);
            sb[2*cc] = pack2(lo, lo);
            if (cc < 6) sb[2*cc+1] = pack2(hi, hi);
        }

        // ---- per-neighbor rows 6..12: 4 packs, init from sb on first row ----
        u64 h[4][13];
        const ulonglong2* w1p = &sW1d[l*49];
        #pragma unroll
        for (int r = 0; r < 7; r++) {
            #pragma unroll
            for (int cc = 0; cc < 7; cc++) {
                ulonglong2 w = w1p[r*7 + cc];
                #pragma unroll
                for (int q = 0; q < 4; q++) {
                    u64 f = (r < 6) ? atQ[q][r] : dQ[q];
                    if (r == 0) {
                        h[q][2*cc] = ffma2(f, w.x, sb[2*cc]);
                        if (cc < 6) h[q][2*cc+1] = ffma2(f, w.y, sb[2*cc+1]);
                    } else {
                        h[q][2*cc] = ffma2(f, w.x, h[q][2*cc]);
                        if (cc < 6) h[q][2*cc+1] = ffma2(f, w.y, h[q][2*cc+1]);
                    }
                }
            }
        }
        #pragma unroll
        for (int q = 0; q < 4; q++)
            #pragma unroll
            for (int c = 0; c < 13; c++) h[q][c] = lrelu2(h[q][c], c06, c04);

        // ---- m = sum over 4 packs of h @ W2, + 4*b2 (packed), single accumulator set ----
        u64 m[6];
        #pragma unroll
        for (int c = 0; c < 6; c++) m[c] = sB2[l*6 + c];
        const ulonglong2* w2p = &sW2d[l*39];
        #pragma unroll
        for (int r = 0; r < 13; r++) {
            #pragma unroll
            for (int cc = 0; cc < 3; cc++) {
                ulonglong2 w = w2p[r*3 + cc];
                #pragma unroll
                for (int q = 0; q < 4; q++) {
                    m[2*cc]   = ffma2(h[q][r], w.x, m[2*cc]);
                    m[2*cc+1] = ffma2(h[q][r], w.y, m[2*cc+1]);
                }
            }
        }

        // ---- reduce over 16 neighbors: in-thread (8) then pair butterfly ----
        float msg[6];
        #pragma unroll
        for (int c = 0; c < 6; c++) {
            float lo, hi;
            unpack2(m[c], lo, hi);
            msg[c] = lo + hi;
        }
        #pragma unroll
        for (int c = 0; c < 6; c++)
            msg[c] += __shfl_xor_sync(0xffffffffu, msg[c], 1);

        // ---- GroupNorm(2 groups of 3) + lrelu + residual (redundant per lane) ----
        float mu0 = (msg[0] + msg[1] + msg[2]) * (1.0f/3.0f);
        float mu1 = (msg[3] + msg[4] + msg[5]) * (1.0f/3.0f);
        float ev[6];
        ev[0] = msg[0] - mu0; ev[1] = msg[1] - mu0; ev[2] = msg[2] - mu0;
        ev[3] = msg[3] - mu1; ev[4] = msg[4] - mu1; ev[5] = msg[5] - mu1;
        float rs0 = rsqrtf((ev[0]*ev[0] + ev[1]*ev[1] + ev[2]*ev[2]) * (1.0f/3.0f) + 1e-5f);
        float rs1 = rsqrtf((ev[3]*ev[3] + ev[4]*ev[4] + ev[5]*ev[5]) * (1.0f/3.0f) + 1e-5f);
        #pragma unroll
        for (int c = 0; c < 6; c++) {
            float xn = ev[c] * (c < 3 ? rs0 : rs1);
            float y  = xn * sGW[l*6 + c] + sGB[l*6 + c];
            pe[c] += fmaxf(y, 0.2f * y);
        }
    }

    if (valid) {
        float* o = out + (size_t)p * 6;
        #pragma unroll
        for (int c = sub; c < 6; c += 2) o[c] = pe[c];
    }
}

extern "C" void kernel_launch(void* const* d_in, const int* in_sizes, int n_in,
                              void* d_out, int out_size)
{
    const float* dist = (const float*)d_in[0];
    const float* at   = (const float*)d_in[1];
    const float* W1   = (const float*)d_in[2];
    const float* b1   = (const float*)d_in[3];
    const float* W2   = (const float*)d_in[4];
    const float* b2   = (const float*)d_in[5];
    const float* gw   = (const float*)d_in[6];
    const float* gb   = (const float*)d_in[7];

    int P = in_sizes[0] / KNB;                    // B*N points
    int blocks = (P * 2 + TPB - 1) / TPB;
    atom_mp_kernel<<<blocks, TPB>>>(dist, at, W1, b1, W2, b2, gw, gb,
                                    (float*)d_out, P);
}

// round 7
// speedup vs baseline: 1.2909x; 1.0356x over previous
#include <cuda_runtime.h>

#define KNB 16
#define NL 3
#define TPB 128

typedef unsigned long long u64;

__device__ __forceinline__ u64 pack2(float lo, float hi){
    u64 r; asm("mov.b64 %0, {%1,%2};" : "=l"(r) : "f"(lo), "f"(hi)); return r;
}
__device__ __forceinline__ void unpack2(u64 v, float& lo, float& hi){
    asm("mov.b64 {%0,%1}, %2;" : "=f"(lo), "=f"(hi) : "l"(v));
}
__device__ __forceinline__ u64 ffma2(u64 a, u64 b, u64 c){
    u64 d; asm("fma.rn.f32x2 %0, %1, %2, %3;" : "=l"(d) : "l"(a), "l"(b), "l"(c)); return d;
}
__device__ __forceinline__ u64 fmul2(u64 a, u64 b){
    u64 d; asm("mul.rn.f32x2 %0, %1, %2;" : "=l"(d) : "l"(a), "l"(b)); return d;
}

// lrelu(x) = max(x, 0.2x) = 0.6x + 0.4|x|   (branchless, packed)
__device__ __forceinline__ u64 lrelu2(u64 x, u64 c06, u64 c04){
    u64 ax = x & 0x7fffffff7fffffffULL;
    return ffma2(ax, c04, fmul2(x, c06));
}

__global__ __launch_bounds__(TPB, 4)
void atom_mp_kernel(const float* __restrict__ dist,
                    const float* __restrict__ at,
                    const float* __restrict__ W1, const float* __restrict__ b1,
                    const float* __restrict__ W2, const float* __restrict__ b2,
                    const float* __restrict__ gw, const float* __restrict__ gb,
                    float* __restrict__ out, int P)
{
    // base tables (rows 0..5, natural column pairs)
    __shared__ u64 sW1c[NL*6*8];
    __shared__ u64 sB1c[NL*8];
    // column-major W1 rows 6..11: [l][c][k] = {splat W1[6+2k][c], splat W1[7+2k][c]}
    __shared__ ulonglong2 sW1cm[NL*13*3];
    __shared__ u64 sW1r12[NL*13];         // splat W1[12][c] (dist row)
    __shared__ ulonglong2 sW2d[NL*13*3];  // [l][c][cc] = {splat W2[c][2cc], splat W2[c][2cc+1]}
    __shared__ u64  sB2[NL*6];            // 4*b2 splatted
    __shared__ float sGW[NL*6], sGB[NL*6];

    const int tid = threadIdx.x;
    for (int i = tid; i < NL*6*7; i += TPB) {
        int l = i / 42, rr = i % 42, r = rr / 7, cc = rr % 7;
        int c0 = 2*cc;
        float w0 = W1[l*169 + r*13 + c0];
        float w1 = (c0 + 1 < 13) ? W1[l*169 + r*13 + c0 + 1] : 0.0f;
        sW1c[(l*6 + r)*8 + cc] = pack2(w0, w1);
    }
    if (tid < NL*8) {
        int l = tid / 8, cc = tid % 8;
        float v0 = (2*cc < 13)     ? b1[l*13 + 2*cc]     : 0.0f;
        float v1 = (2*cc + 1 < 13) ? b1[l*13 + 2*cc + 1] : 0.0f;
        sB1c[tid] = pack2(v0, v1);
    }
    for (int i = tid; i < NL*13*3; i += TPB) {
        int l = i / 39, rr = i % 39, c = rr / 3, k = rr % 3;
        float w0 = W1[l*169 + (6 + 2*k)*13 + c];
        float w1 = W1[l*169 + (7 + 2*k)*13 + c];
        sW1cm[i] = make_ulonglong2(pack2(w0, w0), pack2(w1, w1));
    }
    if (tid < NL*13) {
        int l = tid / 13, c = tid % 13;
        float w = W1[l*169 + 12*13 + c];
        sW1r12[tid] = pack2(w, w);
    }
    for (int i = tid; i < NL*13*3; i += TPB) {
        int l = i / 39, rr = i % 39, c = rr / 3, cc = rr % 3;
        float w0 = W2[l*78 + c*6 + 2*cc];
        float w1 = W2[l*78 + c*6 + 2*cc + 1];
        sW2d[i] = make_ulonglong2(pack2(w0, w0), pack2(w1, w1));
    }
    if (tid < NL*6) {
        float b4 = 4.0f * b2[tid];
        sB2[tid] = pack2(b4, b4);
        sGW[tid] = gw[tid]; sGB[tid] = gb[tid];
    }
    __syncthreads();

    int gt  = blockIdx.x * TPB + tid;
    int p0  = gt >> 1;                 // point index (2 threads per point)
    int sub = gt & 1;                  // which 8-neighbor half
    bool valid = (p0 < P);
    int p = valid ? p0 : (P - 1);      // clamp: keep warps converged for shfl

    // ---- load 8 neighbors: 48 contiguous atomtype floats + 8 dists ----
    float arr[48];
    {
        const float4* atq = (const float4*)(at + (size_t)p * (KNB*6) + sub * 48);
        float4* arv = (float4*)arr;
        #pragma unroll
        for (int i = 0; i < 12; i++) arv[i] = atq[i];
    }
    u64 atQ[4][6];                     // pack q = neighbors (2q, 2q+1)
    #pragma unroll
    for (int q = 0; q < 4; q++)
        #pragma unroll
        for (int d = 0; d < 6; d++)
            atQ[q][d] = pack2(arr[12*q + d], arr[12*q + 6 + d]);

    u64 dQ[4];
    {
        float darr[8];
        float4* drv = (float4*)darr;
        const float4* dq4 = (const float4*)(dist + (size_t)p * KNB + sub * 8);
        drv[0] = dq4[0]; drv[1] = dq4[1];
        #pragma unroll
        for (int q = 0; q < 4; q++) dQ[q] = pack2(darr[2*q], darr[2*q+1]);
    }

    const u64 c06 = pack2(0.6f, 0.6f), c04 = pack2(0.4f, 0.4f);

    float pe[6];
    #pragma unroll
    for (int c = 0; c < 6; c++) pe[c] = 1.0f;

    #pragma unroll 1
    for (int l = 0; l < NL; l++) {
        // ---- shared base: b1 + pe @ W1[rows 0..5], column-packed (neighbor-invariant) ----
        u64 bc[7];
        #pragma unroll
        for (int cc = 0; cc < 7; cc++) bc[cc] = sB1c[l*8 + cc];
        #pragma unroll
        for (int r = 0; r < 6; r++) {
            u64 f = pack2(pe[r], pe[r]);
            #pragma unroll
            for (int cc = 0; cc < 7; cc++)
                bc[cc] = ffma2(f, sW1c[(l*6 + r)*8 + cc], bc[cc]);
        }

        // ---- fused c-major: per hidden column c, build hq[4], lrelu, fold into m ----
        u64 m[6];
        #pragma unroll
        for (int j = 0; j < 6; j++) m[j] = sB2[l*6 + j];

        const ulonglong2* wcm = &sW1cm[l*39];
        const u64*        w12 = &sW1r12[l*13];
        const ulonglong2* w2p = &sW2d[l*39];

        #pragma unroll
        for (int c = 0; c < 13; c++) {
            float blo, bhi;
            unpack2(bc[c >> 1], blo, bhi);
            float b = (c & 1) ? bhi : blo;
            u64 sp = pack2(b, b);

            ulonglong2 wa = wcm[c*3 + 0];
            ulonglong2 wb = wcm[c*3 + 1];
            ulonglong2 wc = wcm[c*3 + 2];
            u64 wd = w12[c];

            u64 hq[4];
            #pragma unroll
            for (int q = 0; q < 4; q++) hq[q] = ffma2(atQ[q][0], wa.x, sp);
            #pragma unroll
            for (int q = 0; q < 4; q++) hq[q] = ffma2(atQ[q][1], wa.y, hq[q]);
            #pragma unroll
            for (int q = 0; q < 4; q++) hq[q] = ffma2(atQ[q][2], wb.x, hq[q]);
            #pragma unroll
            for (int q = 0; q < 4; q++) hq[q] = ffma2(atQ[q][3], wb.y, hq[q]);
            #pragma unroll
            for (int q = 0; q < 4; q++) hq[q] = ffma2(atQ[q][4], wc.x, hq[q]);
            #pragma unroll
            for (int q = 0; q < 4; q++) hq[q] = ffma2(atQ[q][5], wc.y, hq[q]);
            #pragma unroll
            for (int q = 0; q < 4; q++) hq[q] = ffma2(dQ[q], wd, hq[q]);
            #pragma unroll
            for (int q = 0; q < 4; q++) hq[q] = lrelu2(hq[q], c06, c04);

            ulonglong2 v0 = w2p[c*3 + 0];
            ulonglong2 v1 = w2p[c*3 + 1];
            ulonglong2 v2 = w2p[c*3 + 2];
            #pragma unroll
            for (int q = 0; q < 4; q++) {
                m[0] = ffma2(hq[q], v0.x, m[0]);
                m[1] = ffma2(hq[q], v0.y, m[1]);
                m[2] = ffma2(hq[q], v1.x, m[2]);
                m[3] = ffma2(hq[q], v1.y, m[3]);
                m[4] = ffma2(hq[q], v2.x, m[4]);
                m[5] = ffma2(hq[q], v2.y, m[5]);
            }
        }

        // ---- reduce over 16 neighbors: in-thread (8) then pair butterfly ----
        float msg[6];
        #pragma unroll
        for (int c = 0; c < 6; c++) {
            float lo, hi;
            unpack2(m[c], lo, hi);
            msg[c] = lo + hi;
        }
        #pragma unroll
        for (int c = 0; c < 6; c++)
            msg[c] += __shfl_xor_sync(0xffffffffu, msg[c], 1);

        // ---- GroupNorm(2 groups of 3) + lrelu + residual (redundant per lane) ----
        float mu0 = (msg[0] + msg[1] + msg[2]) * (1.0f/3.0f);
        float mu1 = (msg[3] + msg[4] + msg[5]) * (1.0f/3.0f);
        float ev[6];
        ev[0] = msg[0] - mu0; ev[1] = msg[1] - mu0; ev[2] = msg[2] - mu0;
        ev[3] = msg[3] - mu1; ev[4] = msg[4] - mu1; ev[5] = msg[5] - mu1;
        float rs0 = rsqrtf((ev[0]*ev[0] + ev[1]*ev[1] + ev[2]*ev[2]) * (1.0f/3.0f) + 1e-5f);
        float rs1 = rsqrtf((ev[3]*ev[3] + ev[4]*ev[4] + ev[5]*ev[5]) * (1.0f/3.0f) + 1e-5f);
        #pragma unroll
        for (int c = 0; c < 6; c++) {
            float xn = ev[c] * (c < 3 ? rs0 : rs1);
            float y  = xn * sGW[l*6 + c] + sGB[l*6 + c];
            pe[c] += fmaxf(y, 0.2f * y);
        }
    }

    if (valid) {
        float* o = out + (size_t)p * 6;
        #pragma unroll
        for (int c = sub; c < 6; c += 2) o[c] = pe[c];
    }
}

extern "C" void kernel_launch(void* const* d_in, const int* in_sizes, int n_in,
                              void* d_out, int out_size)
{
    const float* dist = (const float*)d_in[0];
    const float* at   = (const float*)d_in[1];
    const float* W1   = (const float*)d_in[2];
    const float* b1   = (const float*)d_in[3];
    const float* W2   = (const float*)d_in[4];
    const float* b2   = (const float*)d_in[5];
    const float* gw   = (const float*)d_in[6];
    const float* gb   = (const float*)d_in[7];

    int P = in_sizes[0] / KNB;                    // B*N points
    int blocks = (P * 2 + TPB - 1) / TPB;
    atom_mp_kernel<<<blocks, TPB>>>(dist, at, W1, b1, W2, b2, gw, gb,
                                    (float*)d_out, P);
}